// round 10
// baseline (speedup 1.0000x reference)
#include <cuda_runtime.h>
#include <cuda_fp16.h>
#include <math.h>
#include <stdint.h>

// Problem constants (fixed by the reference).
#define NN    10000
#define FIN   70
#define HEADS 4
#define HID   256
#define C1    (HEADS*HID)      // 1024
#define EMX   160000
#define ETMX  (EMX + NN)       // edges + self loops

// ---------------- scratch (device globals; no allocation allowed) ----------
__device__ __half   g_h1h  [(size_t)NN * C1];   // GAT1 pre-aggregation features
__device__ __half   g_out1h[(size_t)NN * C1];   // GAT1 output (relu'd), GEMM2 input
__device__ __half   g_h2h  [(size_t)NN * HID];  // GAT2 pre-aggregation features
__device__ float    g_out2 [(size_t)NN * HID];
__device__ float    g_as1 [NN * HEADS];
__device__ float    g_ad1 [NN * HEADS];
__device__ float    g_den1[NN * HEADS];
__device__ float    g_e1  [(size_t)ETMX * HEADS];
__device__ float    g_as2 [NN];
__device__ float    g_ad2 [NN];
__device__ float    g_den2[NN];
__device__ float    g_e2  [ETMX];
__device__ float    g_pooled[HID];
// CSR by destination
__device__ int      g_deg   [NN];
__device__ int      g_rowptr[NN + 1];
__device__ int      g_cursor[NN];
__device__ int      g_csr_src[ETMX];
__device__ int      g_csr_eid[ETMX];

// ---------------- helpers ----------------------------------------------------
__device__ __forceinline__ void edge_sd(const int* ei, int E, int e, int& s, int& d) {
    if (e < E) { s = ei[e]; d = ei[E + e]; }
    else       { s = d = e - E; }           // self loop
}
__device__ __forceinline__ uint32_t f2tf32(float v) {
    uint32_t u;
    asm("cvt.rna.tf32.f32 %0, %1;" : "=r"(u) : "f"(v));
    return u;
}
__device__ __forceinline__ float lda(const float* p)  { return *p; }
__device__ __forceinline__ float lda(const __half* p) { return __half2float(*p); }

// ---------------- tf32 mma.sync GEMM (half output, reg-prefetch) -------------
// C[M,N](half) = A[M,K] @ B[K,N](fp32 weights). tf32 in, fp32 accum.
// CTA 64x128, 4 warps, warp = 64(M)x32(N) of m16n8k8 frags.
#define GBM 64
#define GBN 128
#define GBK 32

template <typename TA>
__global__ __launch_bounds__(128) void gemm_mma(
    const TA* __restrict__ A, const float* __restrict__ B,
    __half* __restrict__ C, int M, int N, int K)
{
    __shared__ uint32_t As[GBM][GBK + 4];    // [m][k]
    __shared__ uint32_t Bs[GBK][GBN + 8];    // [k][n]

    const int tid  = threadIdx.x;
    const int wid  = tid >> 5;
    const int lane = tid & 31;
    const int grp  = lane >> 2;       // 0..7
    const int sub  = lane & 3;        // 0..3
    const int bm = blockIdx.y * GBM;
    const int bn = blockIdx.x * GBN;
    const int wn = wid * 32;

    float acc[4][4][4];
#pragma unroll
    for (int i = 0; i < 4; i++)
#pragma unroll
        for (int j = 0; j < 4; j++)
#pragma unroll
            for (int r = 0; r < 4; r++) acc[i][j][r] = 0.f;

    float  a_pre[16];
    float4 b_pre[8];

    // prefetch tile k0=0
#pragma unroll
    for (int it = 0; it < 16; it++) {
        int idx = it * 128 + tid;
        int r = idx >> 5, c = idx & 31;
        int gm = bm + r;
        a_pre[it] = (gm < M && c < K) ? lda(&A[(size_t)gm * K + c]) : 0.f;
    }
#pragma unroll
    for (int it = 0; it < 8; it++) {
        int f4 = it * 128 + tid;
        int kr = f4 >> 5, c4 = (f4 & 31) << 2;
        b_pre[it] = (kr < K) ? *(const float4*)&B[(size_t)kr * N + bn + c4]
                             : make_float4(0.f, 0.f, 0.f, 0.f);
    }

    for (int k0 = 0; k0 < K; k0 += GBK) {
        // commit prefetched tile to smem (tf32 convert on store)
#pragma unroll
        for (int it = 0; it < 16; it++) {
            int idx = it * 128 + tid;
            As[idx >> 5][idx & 31] = f2tf32(a_pre[it]);
        }
#pragma unroll
        for (int it = 0; it < 8; it++) {
            int f4 = it * 128 + tid;
            int kr = f4 >> 5, c4 = (f4 & 31) << 2;
            Bs[kr][c4 + 0] = f2tf32(b_pre[it].x);
            Bs[kr][c4 + 1] = f2tf32(b_pre[it].y);
            Bs[kr][c4 + 2] = f2tf32(b_pre[it].z);
            Bs[kr][c4 + 3] = f2tf32(b_pre[it].w);
        }
        __syncthreads();

        // issue global loads for NEXT tile while MMAs run on this one
        const int kn = k0 + GBK;
        if (kn < K) {
#pragma unroll
            for (int it = 0; it < 16; it++) {
                int idx = it * 128 + tid;
                int r = idx >> 5, c = idx & 31;
                int gm = bm + r, gk = kn + c;
                a_pre[it] = (gm < M && gk < K) ? lda(&A[(size_t)gm * K + gk]) : 0.f;
            }
#pragma unroll
            for (int it = 0; it < 8; it++) {
                int f4 = it * 128 + tid;
                int kr = f4 >> 5, c4 = (f4 & 31) << 2;
                int gk = kn + kr;
                b_pre[it] = (gk < K) ? *(const float4*)&B[(size_t)gk * N + bn + c4]
                                     : make_float4(0.f, 0.f, 0.f, 0.f);
            }
        }

#pragma unroll
        for (int kk = 0; kk < 4; kk++) {          // 4 kfrags of 8
            const int kf = kk * 8;
            uint32_t a[4][4], b[4][2];
#pragma unroll
            for (int i = 0; i < 4; i++) {
                int m0 = i * 16;
                a[i][0] = As[m0 + grp    ][kf + sub    ];
                a[i][1] = As[m0 + 8 + grp][kf + sub    ];
                a[i][2] = As[m0 + grp    ][kf + 4 + sub];
                a[i][3] = As[m0 + 8 + grp][kf + 4 + sub];
            }
#pragma unroll
            for (int j = 0; j < 4; j++) {
                int n0 = wn + j * 8;
                b[j][0] = Bs[kf + sub    ][n0 + grp];
                b[j][1] = Bs[kf + 4 + sub][n0 + grp];
            }
#pragma unroll
            for (int i = 0; i < 4; i++)
#pragma unroll
                for (int j = 0; j < 4; j++)
                    asm volatile(
                        "mma.sync.aligned.m16n8k8.row.col.f32.tf32.tf32.f32 "
                        "{%0,%1,%2,%3}, {%4,%5,%6,%7}, {%8,%9}, {%0,%1,%2,%3};"
                        : "+f"(acc[i][j][0]), "+f"(acc[i][j][1]),
                          "+f"(acc[i][j][2]), "+f"(acc[i][j][3])
                        : "r"(a[i][0]), "r"(a[i][1]), "r"(a[i][2]), "r"(a[i][3]),
                          "r"(b[j][0]), "r"(b[j][1]));
        }
        __syncthreads();
    }

    // Epilogue: half2 stores. c0/c1 at (row, col), c2/c3 at (row+8, col).
#pragma unroll
    for (int i = 0; i < 4; i++) {
#pragma unroll
        for (int j = 0; j < 4; j++) {
            int col = bn + wn + j * 8 + sub * 2;
            int r0 = bm + i * 16 + grp;
            if (r0 < M)
                *(__half2*)&C[(size_t)r0 * N + col] =
                    __floats2half2_rn(acc[i][j][0], acc[i][j][1]);
            if (r0 + 8 < M)
                *(__half2*)&C[(size_t)(r0 + 8) * N + col] =
                    __floats2half2_rn(acc[i][j][2], acc[i][j][3]);
        }
    }
}

// ---------------- CSR build --------------------------------------------------
__global__ void init_all() {
    int i = blockIdx.x * blockDim.x + threadIdx.x;
    if (i < NN * HEADS) g_den1[i] = 0.f;
    if (i < NN) { g_den2[i] = 0.f; g_deg[i] = 0; }
    if (i < HID) g_pooled[i] = 0.f;
}

__global__ void csr_count(const int* __restrict__ ei, int E, int n) {
    int e = blockIdx.x * blockDim.x + threadIdx.x;
    if (e >= E + n) return;
    int d = (e < E) ? ei[E + e] : (e - E);
    atomicAdd(&g_deg[d], 1);
}

// Single-block exclusive scan of g_deg -> g_rowptr/g_cursor. 1024 threads.
__global__ __launch_bounds__(1024) void scan_deg(int n, int etot) {
    __shared__ int s_ws[32];
    __shared__ int s_tot;
    const int t = threadIdx.x, lane = t & 31, wid = t >> 5;
    int carry = 0;
    for (int base = 0; base < n; base += 1024) {
        int i = base + t;
        int v = (i < n) ? g_deg[i] : 0;
        int x = v;
#pragma unroll
        for (int o = 1; o < 32; o <<= 1) {
            int y = __shfl_up_sync(0xffffffffu, x, o);
            if (lane >= o) x += y;
        }
        if (lane == 31) s_ws[wid] = x;
        __syncthreads();
        if (wid == 0) {
            int y = s_ws[lane];
#pragma unroll
            for (int o = 1; o < 32; o <<= 1) {
                int z = __shfl_up_sync(0xffffffffu, y, o);
                if (lane >= o) y += z;
            }
            s_ws[lane] = y;
            if (lane == 31) s_tot = y;
        }
        __syncthreads();
        int incl = x + (wid ? s_ws[wid - 1] : 0) + carry;
        if (i < n) { g_rowptr[i] = incl - v; g_cursor[i] = incl - v; }
        carry += s_tot;
        __syncthreads();
    }
    if (t == 0) g_rowptr[n] = etot;
}

__global__ void csr_scatter(const int* __restrict__ ei, int E, int n) {
    int e = blockIdx.x * blockDim.x + threadIdx.x;
    if (e >= E + n) return;
    int s, d; edge_sd(ei, E, e, s, d);
    int pos = atomicAdd(&g_cursor[d], 1);
    g_csr_src[pos] = s;
    g_csr_eid[pos] = e;
}

// ---------------- layer 1 ----------------------------------------------------
// per (node, head) dots with att vectors; h1 read as half2.
__global__ void att1_kernel(const float* __restrict__ asrc,
                            const float* __restrict__ adst, int n)
{
    int wid = (blockIdx.x * blockDim.x + threadIdx.x) >> 5;
    int lane = threadIdx.x & 31;
    if (wid >= n * HEADS) return;
    int node = wid >> 2, h = wid & 3;
    const __half2* x = (const __half2*)(g_h1h + (size_t)node * C1 + h * HID);
    const float* s = asrc + h * HID;
    const float* d = adst + h * HID;
    float ss = 0.f, dd = 0.f;
#pragma unroll
    for (int i = lane; i < HID / 2; i += 32) {
        float2 v = __half22float2(x[i]);
        ss = fmaf(v.x, s[2 * i], fmaf(v.y, s[2 * i + 1], ss));
        dd = fmaf(v.x, d[2 * i], fmaf(v.y, d[2 * i + 1], dd));
    }
#pragma unroll
    for (int o = 16; o; o >>= 1) {
        ss += __shfl_down_sync(0xffffffffu, ss, o);
        dd += __shfl_down_sync(0xffffffffu, dd, o);
    }
    if (lane == 0) { g_as1[node * HEADS + h] = ss; g_ad1[node * HEADS + h] = dd; }
}

// Fused leaky_relu + exp + denom (no segment-max: scores bounded, exp safe;
// alpha = exp(e)/sum exp(e) identical to max-shifted form).
__global__ void edge_fused1(const int* __restrict__ ei, int E, int n) {
    int e = blockIdx.x * blockDim.x + threadIdx.x;
    if (e >= E + n) return;
    int s, d; edge_sd(ei, E, e, s, d);
    float4 a = *(const float4*)&g_as1[s * HEADS];
    float4 b = *(const float4*)&g_ad1[d * HEADS];
    float v[4] = {a.x + b.x, a.y + b.y, a.z + b.z, a.w + b.w};
    float ex[4];
#pragma unroll
    for (int h = 0; h < 4; h++) {
        float t = v[h] > 0.f ? v[h] : 0.2f * v[h];
        ex[h] = expf(t);
        atomicAdd(&g_den1[d * HEADS + h], ex[h]);
    }
    *(float4*)&g_e1[(size_t)e * HEADS] = make_float4(ex[0], ex[1], ex[2], ex[3]);
}

// One block per dst node; gathers half h1 rows (L2-resident), fp32 accum.
// Bias+ReLU fused; writes half out1 for GEMM2.
#define CHUNK 64
__global__ __launch_bounds__(256) void aggregate1_csr(const float* __restrict__ b1, int n) {
    int d = blockIdx.x;
    int t = threadIdx.x;
    int beg = g_rowptr[d], end = g_rowptr[d + 1];
    int h = t >> 6;                  // 0..3
    int c = (t & 63) << 2;           // 0..252

    __shared__ float s_invden[HEADS];
    __shared__ int   s_src[CHUNK];
    __shared__ float s_alpha[CHUNK * HEADS];
    if (t < HEADS) s_invden[t] = 1.f / (g_den1[d * HEADS + t] + 1e-16f);
    __syncthreads();

    float4 acc = make_float4(0.f, 0.f, 0.f, 0.f);
    for (int cb = beg; cb < end; cb += CHUNK) {
        int m = min(CHUNK, end - cb);
        if (t < m) {
            int pos = cb + t;
            int e = g_csr_eid[pos];
            s_src[t] = g_csr_src[pos];
            float4 ex = *(const float4*)&g_e1[(size_t)e * HEADS];
            s_alpha[t * 4 + 0] = ex.x * s_invden[0];
            s_alpha[t * 4 + 1] = ex.y * s_invden[1];
            s_alpha[t * 4 + 2] = ex.z * s_invden[2];
            s_alpha[t * 4 + 3] = ex.w * s_invden[3];
        }
        __syncthreads();
        for (int j = 0; j < m; j++) {
            int s = s_src[j];
            float a = s_alpha[j * 4 + h];
            uint2 u = *(const uint2*)&g_h1h[(size_t)s * C1 + h * HID + c];
            float2 f0 = __half22float2(*(__half2*)&u.x);
            float2 f1 = __half22float2(*(__half2*)&u.y);
            acc.x = fmaf(a, f0.x, acc.x);
            acc.y = fmaf(a, f0.y, acc.y);
            acc.z = fmaf(a, f1.x, acc.z);
            acc.w = fmaf(a, f1.y, acc.w);
        }
        __syncthreads();
    }
    float4 bv = *(const float4*)&b1[h * HID + c];
    __half2 o0 = __floats2half2_rn(fmaxf(acc.x + bv.x, 0.f), fmaxf(acc.y + bv.y, 0.f));
    __half2 o1 = __floats2half2_rn(fmaxf(acc.z + bv.z, 0.f), fmaxf(acc.w + bv.w, 0.f));
    uint2 o; o.x = *(uint32_t*)&o0; o.y = *(uint32_t*)&o1;
    *(uint2*)&g_out1h[(size_t)d * C1 + h * HID + c] = o;
}

// ---------------- layer 2 ----------------------------------------------------
__global__ void att2_kernel(const float* __restrict__ asrc,
                            const float* __restrict__ adst, int n)
{
    int wid = (blockIdx.x * blockDim.x + threadIdx.x) >> 5;
    int lane = threadIdx.x & 31;
    if (wid >= n) return;
    const __half2* x = (const __half2*)(g_h2h + (size_t)wid * HID);
    float ss = 0.f, dd = 0.f;
#pragma unroll
    for (int i = lane; i < HID / 2; i += 32) {
        float2 v = __half22float2(x[i]);
        ss = fmaf(v.x, asrc[2 * i], fmaf(v.y, asrc[2 * i + 1], ss));
        dd = fmaf(v.x, adst[2 * i], fmaf(v.y, adst[2 * i + 1], dd));
    }
#pragma unroll
    for (int o = 16; o; o >>= 1) {
        ss += __shfl_down_sync(0xffffffffu, ss, o);
        dd += __shfl_down_sync(0xffffffffu, dd, o);
    }
    if (lane == 0) { g_as2[wid] = ss; g_ad2[wid] = dd; }
}

__global__ void edge_fused2(const int* __restrict__ ei, int E, int n) {
    int e = blockIdx.x * blockDim.x + threadIdx.x;
    if (e >= E + n) return;
    int s, d; edge_sd(ei, E, e, s, d);
    float v = g_as2[s] + g_ad2[d];
    v = v > 0.f ? v : 0.2f * v;
    float ex = expf(v);
    g_e2[e] = ex;
    atomicAdd(&g_den2[d], ex);
}

// 4 dst nodes per 256-thread block; 64 lanes per node. Bias fused.
__global__ __launch_bounds__(256) void aggregate2_csr(const float* __restrict__ b2, int n) {
    int sub = threadIdx.x >> 6;
    int lane = threadIdx.x & 63;
    int d = blockIdx.x * 4 + sub;
    if (d >= n) return;
    int beg = g_rowptr[d], end = g_rowptr[d + 1];
    float invden = 1.f / (g_den2[d] + 1e-16f);
    int c = lane << 2;
    float4 acc = make_float4(0.f, 0.f, 0.f, 0.f);
    for (int k = beg; k < end; k++) {
        int s = g_csr_src[k];
        int e = g_csr_eid[k];
        float a = g_e2[e] * invden;
        uint2 u = *(const uint2*)&g_h2h[(size_t)s * HID + c];
        float2 f0 = __half22float2(*(__half2*)&u.x);
        float2 f1 = __half22float2(*(__half2*)&u.y);
        acc.x = fmaf(a, f0.x, acc.x);
        acc.y = fmaf(a, f0.y, acc.y);
        acc.z = fmaf(a, f1.x, acc.z);
        acc.w = fmaf(a, f1.y, acc.w);
    }
    float4 bv = *(const float4*)&b2[c];
    *(float4*)&g_out2[(size_t)d * HID + c] =
        make_float4(acc.x + bv.x, acc.y + bv.y, acc.z + bv.z, acc.w + bv.w);
}

// relu + column-sum pooling
__global__ void pool_kernel(int n) {
    int c = threadIdx.x;        // 256
    float acc = 0.f;
    for (int r = blockIdx.x; r < n; r += gridDim.x)
        acc += fmaxf(g_out2[(size_t)r * HID + c], 0.f);
    atomicAdd(&g_pooled[c], acc);
}

// mean -> Linear(256,128) -> exact GELU -> Linear(128,1)
__global__ void final_kernel(const float* __restrict__ Wv1, const float* __restrict__ bv1,
                             const float* __restrict__ Wv2, const float* __restrict__ bv2,
                             float* __restrict__ out, int n)
{
    __shared__ float p[HID];
    __shared__ float red[128];
    int t = threadIdx.x;        // 128
    float inv = 1.f / (float)n;
    p[t]       = g_pooled[t] * inv;
    p[t + 128] = g_pooled[t + 128] * inv;
    __syncthreads();
    float acc = bv1[t];
#pragma unroll 8
    for (int k = 0; k < HID; k++) acc = fmaf(p[k], Wv1[k * 128 + t], acc);
    float g = 0.5f * acc * (1.f + erff(acc * 0.70710678118654752f));
    red[t] = g * Wv2[t];
    __syncthreads();
#pragma unroll
    for (int o = 64; o; o >>= 1) {
        if (t < o) red[t] += red[t + o];
        __syncthreads();
    }
    if (t == 0) out[0] = red[0] + bv2[0];
}

// ---------------- launcher ---------------------------------------------------
extern "C" void kernel_launch(void* const* d_in, const int* in_sizes, int n_in,
                              void* d_out, int out_size)
{
    const float* X   = (const float*)d_in[0];
    const int*   EI  = (const int*)  d_in[1];
    // d_in[2] edge_attr: ignored (GATConv has no edge_dim)
    const float* W1  = (const float*)d_in[3];
    const float* as1 = (const float*)d_in[4];
    const float* ad1 = (const float*)d_in[5];
    const float* b1  = (const float*)d_in[6];
    const float* W2  = (const float*)d_in[7];
    const float* as2 = (const float*)d_in[8];
    const float* ad2 = (const float*)d_in[9];
    const float* b2  = (const float*)d_in[10];
    const float* Wv1 = (const float*)d_in[11];
    const float* bv1 = (const float*)d_in[12];
    const float* Wv2 = (const float*)d_in[13];
    const float* bv2 = (const float*)d_in[14];
    float* out = (float*)d_out;

    int n = in_sizes[0] / FIN;       // 10000
    int E = in_sizes[1] / 2;         // 160000
    int etot = E + n;
    int mtiles = (n + GBM - 1) / GBM;    // 157

    __half *p_h1h, *p_out1h, *p_h2h;
    cudaGetSymbolAddress((void**)&p_h1h,   g_h1h);
    cudaGetSymbolAddress((void**)&p_out1h, g_out1h);
    cudaGetSymbolAddress((void**)&p_h2h,   g_h2h);

    // ---- init + CSR build ----
    init_all<<<(n * HEADS + 255) / 256, 256>>>();
    csr_count<<<(etot + 255) / 256, 256>>>(EI, E, n);
    scan_deg<<<1, 1024>>>(n, etot);
    csr_scatter<<<(etot + 255) / 256, 256>>>(EI, E, n);

    // ---- layer 1: h1 = X @ W1 (tf32 mma.sync, half out) ----
    {
        dim3 grid(C1 / GBN, mtiles);
        gemm_mma<float><<<grid, 128>>>(X, W1, p_h1h, n, C1, FIN);
    }
    att1_kernel<<<(n * HEADS * 32 + 255) / 256, 256>>>(as1, ad1, n);
    edge_fused1<<<(etot + 255) / 256, 256>>>(EI, E, n);
    aggregate1_csr<<<n, 256>>>(b1, n);

    // ---- layer 2: h2 = out1 @ W2 (half A, half out) ----
    {
        dim3 grid(HID / GBN, mtiles);
        gemm_mma<__half><<<grid, 128>>>(p_out1h, W2, p_h2h, n, HID, C1);
    }
    att2_kernel<<<(n * 32 + 255) / 256, 256>>>(as2, ad2, n);
    edge_fused2<<<(etot + 255) / 256, 256>>>(EI, E, n);
    aggregate2_csr<<<(n + 3) / 4, 256>>>(b2, n);

    // ---- head ----
    pool_kernel<<<128, 256>>>(n);
    final_kernel<<<1, 128>>>(Wv1, bv1, Wv2, bv2, out, n);
}

// round 11
// speedup vs baseline: 1.0894x; 1.0894x over previous
#include <cuda_runtime.h>
#include <cuda_fp16.h>
#include <math.h>
#include <stdint.h>

// Problem constants (fixed by the reference).
#define NN    10000
#define FIN   70
#define HEADS 4
#define HID   256
#define C1    (HEADS*HID)      // 1024
#define EMX   160000
#define ETMX  (EMX + NN)       // edges + self loops

// ---------------- scratch (device globals; no allocation allowed) ----------
__device__ __half   g_h1h  [(size_t)NN * C1];   // GAT1 pre-agg features (gathered)
__device__ float    g_out1 [(size_t)NN * C1];   // GAT1 output, GEMM2 input (fp32)
__device__ __half   g_h2h  [(size_t)NN * HID];  // GAT2 pre-agg features (gathered)
__device__ float    g_out2 [(size_t)NN * HID];
__device__ float    g_as1 [NN * HEADS];
__device__ float    g_ad1 [NN * HEADS];
__device__ float    g_den1[NN * HEADS];
__device__ float    g_e1  [(size_t)ETMX * HEADS];
__device__ float    g_as2 [NN];
__device__ float    g_ad2 [NN];
__device__ float    g_den2[NN];
__device__ float    g_e2  [ETMX];
__device__ float    g_pooled[HID];
// CSR by destination
__device__ int      g_deg   [NN];
__device__ int      g_rowptr[NN + 1];
__device__ int      g_cursor[NN];
__device__ int      g_csr_src[ETMX];
__device__ int      g_csr_eid[ETMX];

// ---------------- helpers ----------------------------------------------------
__device__ __forceinline__ void edge_sd(const int* ei, int E, int e, int& s, int& d) {
    if (e < E) { s = ei[e]; d = ei[E + e]; }
    else       { s = d = e - E; }           // self loop
}
__device__ __forceinline__ uint32_t f2tf32(float v) {
    uint32_t u;
    asm("cvt.rna.tf32.f32 %0, %1;" : "=r"(u) : "f"(v));
    return u;
}
__device__ __forceinline__ void st_pair(float* p, float a, float b) {
    *(float2*)p = make_float2(a, b);
}
__device__ __forceinline__ void st_pair(__half* p, float a, float b) {
    *(__half2*)p = __floats2half2_rn(a, b);
}

// ---------------- tf32 mma.sync GEMM (R9 structure, templated output) --------
// C[M,N] = A[M,K](fp32) @ B[K,N](fp32). tf32 in, fp32 accum, TC output.
// CTA tile 64x128, 4 warps, warp = 64(M)x32(N) of m16n8k8 frags.
#define GBM 64
#define GBN 128
#define GBK 32

template <typename TC>
__global__ __launch_bounds__(128) void gemm_mma(
    const float* __restrict__ A, const float* __restrict__ B,
    TC* __restrict__ C, int M, int N, int K)
{
    __shared__ uint32_t As[GBM][GBK + 4];    // [m][k]
    __shared__ uint32_t Bs[GBK][GBN + 8];    // [k][n]

    const int tid  = threadIdx.x;
    const int wid  = tid >> 5;
    const int lane = tid & 31;
    const int grp  = lane >> 2;       // 0..7
    const int sub  = lane & 3;        // 0..3
    const int bm = blockIdx.y * GBM;
    const int bn = blockIdx.x * GBN;
    const int wn = wid * 32;          // warp n-offset inside CTA tile

    float acc[4][4][4];
#pragma unroll
    for (int i = 0; i < 4; i++)
#pragma unroll
        for (int j = 0; j < 4; j++)
#pragma unroll
            for (int r = 0; r < 4; r++) acc[i][j][r] = 0.f;

    for (int k0 = 0; k0 < K; k0 += GBK) {
        // A tile 64x32: scalar loads (handles any K alignment), coalesced rows.
#pragma unroll
        for (int it = 0; it < 16; it++) {
            int idx = it * 128 + tid;
            int r = idx >> 5, c = idx & 31;
            int gm = bm + r, gk = k0 + c;
            float v = (gm < M && gk < K) ? A[(size_t)gm * K + gk] : 0.f;
            As[r][c] = f2tf32(v);
        }
        // B tile 32x128: float4 loads (N multiple of 4).
#pragma unroll
        for (int it = 0; it < 8; it++) {
            int f4 = it * 128 + tid;
            int kr = f4 >> 5, c4 = (f4 & 31) << 2;
            int gk = k0 + kr;
            float4 v = make_float4(0.f, 0.f, 0.f, 0.f);
            if (gk < K) v = *(const float4*)&B[(size_t)gk * N + bn + c4];
            Bs[kr][c4 + 0] = f2tf32(v.x);
            Bs[kr][c4 + 1] = f2tf32(v.y);
            Bs[kr][c4 + 2] = f2tf32(v.z);
            Bs[kr][c4 + 3] = f2tf32(v.w);
        }
        __syncthreads();

#pragma unroll
        for (int kk = 0; kk < 4; kk++) {          // 4 kfrags of 8
            const int kf = kk * 8;
            uint32_t a[4][4], b[4][2];
#pragma unroll
            for (int i = 0; i < 4; i++) {
                int m0 = i * 16;
                a[i][0] = As[m0 + grp    ][kf + sub    ];
                a[i][1] = As[m0 + 8 + grp][kf + sub    ];
                a[i][2] = As[m0 + grp    ][kf + 4 + sub];
                a[i][3] = As[m0 + 8 + grp][kf + 4 + sub];
            }
#pragma unroll
            for (int j = 0; j < 4; j++) {
                int n0 = wn + j * 8;
                b[j][0] = Bs[kf + sub    ][n0 + grp];
                b[j][1] = Bs[kf + 4 + sub][n0 + grp];
            }
#pragma unroll
            for (int i = 0; i < 4; i++)
#pragma unroll
                for (int j = 0; j < 4; j++)
                    asm volatile(
                        "mma.sync.aligned.m16n8k8.row.col.f32.tf32.tf32.f32 "
                        "{%0,%1,%2,%3}, {%4,%5,%6,%7}, {%8,%9}, {%0,%1,%2,%3};"
                        : "+f"(acc[i][j][0]), "+f"(acc[i][j][1]),
                          "+f"(acc[i][j][2]), "+f"(acc[i][j][3])
                        : "r"(a[i][0]), "r"(a[i][1]), "r"(a[i][2]), "r"(a[i][3]),
                          "r"(b[j][0]), "r"(b[j][1]));
        }
        __syncthreads();
    }

    // Epilogue: c0/c1 at (row, col), c2/c3 at (row+8, col).
#pragma unroll
    for (int i = 0; i < 4; i++) {
#pragma unroll
        for (int j = 0; j < 4; j++) {
            int col = bn + wn + j * 8 + sub * 2;
            int r0 = bm + i * 16 + grp;
            if (r0 < M)
                st_pair(&C[(size_t)r0 * N + col], acc[i][j][0], acc[i][j][1]);
            if (r0 + 8 < M)
                st_pair(&C[(size_t)(r0 + 8) * N + col], acc[i][j][2], acc[i][j][3]);
        }
    }
}

// ---------------- CSR build --------------------------------------------------
__global__ void init_all() {
    int i = blockIdx.x * blockDim.x + threadIdx.x;
    if (i < NN * HEADS) g_den1[i] = 0.f;
    if (i < NN) { g_den2[i] = 0.f; g_deg[i] = 0; }
    if (i < HID) g_pooled[i] = 0.f;
}

__global__ void csr_count(const int* __restrict__ ei, int E, int n) {
    int e = blockIdx.x * blockDim.x + threadIdx.x;
    if (e >= E + n) return;
    int d = (e < E) ? ei[E + e] : (e - E);
    atomicAdd(&g_deg[d], 1);
}

// Single-block exclusive scan of g_deg -> g_rowptr/g_cursor. 1024 threads.
__global__ __launch_bounds__(1024) void scan_deg(int n, int etot) {
    __shared__ int s_ws[32];
    __shared__ int s_tot;
    const int t = threadIdx.x, lane = t & 31, wid = t >> 5;
    int carry = 0;
    for (int base = 0; base < n; base += 1024) {
        int i = base + t;
        int v = (i < n) ? g_deg[i] : 0;
        int x = v;
#pragma unroll
        for (int o = 1; o < 32; o <<= 1) {
            int y = __shfl_up_sync(0xffffffffu, x, o);
            if (lane >= o) x += y;
        }
        if (lane == 31) s_ws[wid] = x;
        __syncthreads();
        if (wid == 0) {
            int y = s_ws[lane];
#pragma unroll
            for (int o = 1; o < 32; o <<= 1) {
                int z = __shfl_up_sync(0xffffffffu, y, o);
                if (lane >= o) y += z;
            }
            s_ws[lane] = y;
            if (lane == 31) s_tot = y;
        }
        __syncthreads();
        int incl = x + (wid ? s_ws[wid - 1] : 0) + carry;
        if (i < n) { g_rowptr[i] = incl - v; g_cursor[i] = incl - v; }
        carry += s_tot;
        __syncthreads();
    }
    if (t == 0) g_rowptr[n] = etot;
}

__global__ void csr_scatter(const int* __restrict__ ei, int E, int n) {
    int e = blockIdx.x * blockDim.x + threadIdx.x;
    if (e >= E + n) return;
    int s, d; edge_sd(ei, E, e, s, d);
    int pos = atomicAdd(&g_cursor[d], 1);
    g_csr_src[pos] = s;
    g_csr_eid[pos] = e;
}

// ---------------- layer 1 ----------------------------------------------------
// per (node, head) dots with att vectors; h1 read as half2.
__global__ void att1_kernel(const float* __restrict__ asrc,
                            const float* __restrict__ adst, int n)
{
    int wid = (blockIdx.x * blockDim.x + threadIdx.x) >> 5;
    int lane = threadIdx.x & 31;
    if (wid >= n * HEADS) return;
    int node = wid >> 2, h = wid & 3;
    const __half2* x = (const __half2*)(g_h1h + (size_t)node * C1 + h * HID);
    const float* s = asrc + h * HID;
    const float* d = adst + h * HID;
    float ss = 0.f, dd = 0.f;
#pragma unroll
    for (int i = lane; i < HID / 2; i += 32) {
        float2 v = __half22float2(x[i]);
        ss = fmaf(v.x, s[2 * i], fmaf(v.y, s[2 * i + 1], ss));
        dd = fmaf(v.x, d[2 * i], fmaf(v.y, d[2 * i + 1], dd));
    }
#pragma unroll
    for (int o = 16; o; o >>= 1) {
        ss += __shfl_down_sync(0xffffffffu, ss, o);
        dd += __shfl_down_sync(0xffffffffu, dd, o);
    }
    if (lane == 0) { g_as1[node * HEADS + h] = ss; g_ad1[node * HEADS + h] = dd; }
}

// Fused leaky_relu + exp + denom (no segment-max: scores bounded, exp safe;
// alpha = exp(e)/sum exp(e) identical to the max-shifted form).
__global__ void edge_fused1(const int* __restrict__ ei, int E, int n) {
    int e = blockIdx.x * blockDim.x + threadIdx.x;
    if (e >= E + n) return;
    int s, d; edge_sd(ei, E, e, s, d);
    float4 a = *(const float4*)&g_as1[s * HEADS];
    float4 b = *(const float4*)&g_ad1[d * HEADS];
    float v[4] = {a.x + b.x, a.y + b.y, a.z + b.z, a.w + b.w};
    float ex[4];
#pragma unroll
    for (int h = 0; h < 4; h++) {
        float t = v[h] > 0.f ? v[h] : 0.2f * v[h];
        ex[h] = expf(t);
        atomicAdd(&g_den1[d * HEADS + h], ex[h]);
    }
    *(float4*)&g_e1[(size_t)e * HEADS] = make_float4(ex[0], ex[1], ex[2], ex[3]);
}

// One block per dst node; gathers HALF h1 rows, fp32 accum.
// Bias+ReLU fused; writes fp32 out1 (GEMM2 input path stays R9-identical).
#define CHUNK 64
__global__ __launch_bounds__(256) void aggregate1_csr(const float* __restrict__ b1, int n) {
    int d = blockIdx.x;
    int t = threadIdx.x;
    int beg = g_rowptr[d], end = g_rowptr[d + 1];
    int h = t >> 6;                  // 0..3
    int c = (t & 63) << 2;           // 0..252

    __shared__ float s_invden[HEADS];
    __shared__ int   s_src[CHUNK];
    __shared__ float s_alpha[CHUNK * HEADS];
    if (t < HEADS) s_invden[t] = 1.f / (g_den1[d * HEADS + t] + 1e-16f);
    __syncthreads();

    float4 acc = make_float4(0.f, 0.f, 0.f, 0.f);
    for (int cb = beg; cb < end; cb += CHUNK) {
        int m = min(CHUNK, end - cb);
        if (t < m) {
            int pos = cb + t;
            int e = g_csr_eid[pos];
            s_src[t] = g_csr_src[pos];
            float4 ex = *(const float4*)&g_e1[(size_t)e * HEADS];
            s_alpha[t * 4 + 0] = ex.x * s_invden[0];
            s_alpha[t * 4 + 1] = ex.y * s_invden[1];
            s_alpha[t * 4 + 2] = ex.z * s_invden[2];
            s_alpha[t * 4 + 3] = ex.w * s_invden[3];
        }
        __syncthreads();
        for (int j = 0; j < m; j++) {
            int s = s_src[j];
            float a = s_alpha[j * 4 + h];
            uint2 u = *(const uint2*)&g_h1h[(size_t)s * C1 + h * HID + c];
            float2 f0 = __half22float2(*(__half2*)&u.x);
            float2 f1 = __half22float2(*(__half2*)&u.y);
            acc.x = fmaf(a, f0.x, acc.x);
            acc.y = fmaf(a, f0.y, acc.y);
            acc.z = fmaf(a, f1.x, acc.z);
            acc.w = fmaf(a, f1.y, acc.w);
        }
        __syncthreads();
    }
    float4 bv = *(const float4*)&b1[h * HID + c];
    float4 o = make_float4(fmaxf(acc.x + bv.x, 0.f), fmaxf(acc.y + bv.y, 0.f),
                           fmaxf(acc.z + bv.z, 0.f), fmaxf(acc.w + bv.w, 0.f));
    *(float4*)&g_out1[(size_t)d * C1 + h * HID + c] = o;
}

// ---------------- layer 2 ----------------------------------------------------
__global__ void att2_kernel(const float* __restrict__ asrc,
                            const float* __restrict__ adst, int n)
{
    int wid = (blockIdx.x * blockDim.x + threadIdx.x) >> 5;
    int lane = threadIdx.x & 31;
    if (wid >= n) return;
    const __half2* x = (const __half2*)(g_h2h + (size_t)wid * HID);
    float ss = 0.f, dd = 0.f;
#pragma unroll
    for (int i = lane; i < HID / 2; i += 32) {
        float2 v = __half22float2(x[i]);
        ss = fmaf(v.x, asrc[2 * i], fmaf(v.y, asrc[2 * i + 1], ss));
        dd = fmaf(v.x, adst[2 * i], fmaf(v.y, adst[2 * i + 1], dd));
    }
#pragma unroll
    for (int o = 16; o; o >>= 1) {
        ss += __shfl_down_sync(0xffffffffu, ss, o);
        dd += __shfl_down_sync(0xffffffffu, dd, o);
    }
    if (lane == 0) { g_as2[wid] = ss; g_ad2[wid] = dd; }
}

__global__ void edge_fused2(const int* __restrict__ ei, int E, int n) {
    int e = blockIdx.x * blockDim.x + threadIdx.x;
    if (e >= E + n) return;
    int s, d; edge_sd(ei, E, e, s, d);
    float v = g_as2[s] + g_ad2[d];
    v = v > 0.f ? v : 0.2f * v;
    float ex = expf(v);
    g_e2[e] = ex;
    atomicAdd(&g_den2[d], ex);
}

// 4 dst nodes per 256-thread block; 64 lanes per node. Bias fused.
__global__ __launch_bounds__(256) void aggregate2_csr(const float* __restrict__ b2, int n) {
    int sub = threadIdx.x >> 6;
    int lane = threadIdx.x & 63;
    int d = blockIdx.x * 4 + sub;
    if (d >= n) return;
    int beg = g_rowptr[d], end = g_rowptr[d + 1];
    float invden = 1.f / (g_den2[d] + 1e-16f);
    int c = lane << 2;
    float4 acc = make_float4(0.f, 0.f, 0.f, 0.f);
    for (int k = beg; k < end; k++) {
        int s = g_csr_src[k];
        int e = g_csr_eid[k];
        float a = g_e2[e] * invden;
        uint2 u = *(const uint2*)&g_h2h[(size_t)s * HID + c];
        float2 f0 = __half22float2(*(__half2*)&u.x);
        float2 f1 = __half22float2(*(__half2*)&u.y);
        acc.x = fmaf(a, f0.x, acc.x);
        acc.y = fmaf(a, f0.y, acc.y);
        acc.z = fmaf(a, f1.x, acc.z);
        acc.w = fmaf(a, f1.y, acc.w);
    }
    float4 bv = *(const float4*)&b2[c];
    *(float4*)&g_out2[(size_t)d * HID + c] =
        make_float4(acc.x + bv.x, acc.y + bv.y, acc.z + bv.z, acc.w + bv.w);
}

// relu + column-sum pooling
__global__ void pool_kernel(int n) {
    int c = threadIdx.x;        // 256
    float acc = 0.f;
    for (int r = blockIdx.x; r < n; r += gridDim.x)
        acc += fmaxf(g_out2[(size_t)r * HID + c], 0.f);
    atomicAdd(&g_pooled[c], acc);
}

// mean -> Linear(256,128) -> exact GELU -> Linear(128,1)
__global__ void final_kernel(const float* __restrict__ Wv1, const float* __restrict__ bv1,
                             const float* __restrict__ Wv2, const float* __restrict__ bv2,
                             float* __restrict__ out, int n)
{
    __shared__ float p[HID];
    __shared__ float red[128];
    int t = threadIdx.x;        // 128
    float inv = 1.f / (float)n;
    p[t]       = g_pooled[t] * inv;
    p[t + 128] = g_pooled[t + 128] * inv;
    __syncthreads();
    float acc = bv1[t];
#pragma unroll 8
    for (int k = 0; k < HID; k++) acc = fmaf(p[k], Wv1[k * 128 + t], acc);
    float g = 0.5f * acc * (1.f + erff(acc * 0.70710678118654752f));
    red[t] = g * Wv2[t];
    __syncthreads();
#pragma unroll
    for (int o = 64; o; o >>= 1) {
        if (t < o) red[t] += red[t + o];
        __syncthreads();
    }
    if (t == 0) out[0] = red[0] + bv2[0];
}

// ---------------- launcher ---------------------------------------------------
extern "C" void kernel_launch(void* const* d_in, const int* in_sizes, int n_in,
                              void* d_out, int out_size)
{
    const float* X   = (const float*)d_in[0];
    const int*   EI  = (const int*)  d_in[1];
    // d_in[2] edge_attr: ignored (GATConv has no edge_dim)
    const float* W1  = (const float*)d_in[3];
    const float* as1 = (const float*)d_in[4];
    const float* ad1 = (const float*)d_in[5];
    const float* b1  = (const float*)d_in[6];
    const float* W2  = (const float*)d_in[7];
    const float* as2 = (const float*)d_in[8];
    const float* ad2 = (const float*)d_in[9];
    const float* b2  = (const float*)d_in[10];
    const float* Wv1 = (const float*)d_in[11];
    const float* bv1 = (const float*)d_in[12];
    const float* Wv2 = (const float*)d_in[13];
    const float* bv2 = (const float*)d_in[14];
    float* out = (float*)d_out;

    int n = in_sizes[0] / FIN;       // 10000
    int E = in_sizes[1] / 2;         // 160000
    int etot = E + n;
    int mtiles = (n + GBM - 1) / GBM;    // 157

    __half *p_h1h, *p_h2h;
    float  *p_out1;
    cudaGetSymbolAddress((void**)&p_h1h,  g_h1h);
    cudaGetSymbolAddress((void**)&p_out1, g_out1);
    cudaGetSymbolAddress((void**)&p_h2h,  g_h2h);

    // ---- init + CSR build ----
    init_all<<<(n * HEADS + 255) / 256, 256>>>();
    csr_count<<<(etot + 255) / 256, 256>>>(EI, E, n);
    scan_deg<<<1, 1024>>>(n, etot);
    csr_scatter<<<(etot + 255) / 256, 256>>>(EI, E, n);

    // ---- layer 1: h1 = X @ W1 (tf32 mma.sync, half out for gathers) ----
    {
        dim3 grid(C1 / GBN, mtiles);
        gemm_mma<__half><<<grid, 128>>>(X, W1, p_h1h, n, C1, FIN);
    }
    att1_kernel<<<(n * HEADS * 32 + 255) / 256, 256>>>(as1, ad1, n);
    edge_fused1<<<(etot + 255) / 256, 256>>>(EI, E, n);
    aggregate1_csr<<<n, 256>>>(b1, n);

    // ---- layer 2: h2 = out1(fp32) @ W2 (half out for gathers) ----
    {
        dim3 grid(HID / GBN, mtiles);
        gemm_mma<__half><<<grid, 128>>>(p_out1, W2, p_h2h, n, HID, C1);
    }
    att2_kernel<<<(n * 32 + 255) / 256, 256>>>(as2, ad2, n);
    edge_fused2<<<(etot + 255) / 256, 256>>>(EI, E, n);
    aggregate2_csr<<<(n + 3) / 4, 256>>>(b2, n);

    // ---- head ----
    pool_kernel<<<128, 256>>>(n);
    final_kernel<<<1, 128>>>(Wv1, bv1, Wv2, bv2, out, n);
}

// round 14
// speedup vs baseline: 1.2367x; 1.1352x over previous
#include <cuda_runtime.h>
#include <cuda_fp16.h>
#include <math.h>
#include <stdint.h>

// Problem constants (fixed by the reference).
#define NN    10000
#define FIN   70
#define HEADS 4
#define HID   256
#define C1    (HEADS*HID)      // 1024
#define EMX   160000
#define ETMX  (EMX + NN)       // edges + self loops

// ---------------- scratch (device globals; no allocation allowed) ----------
__device__ __half   g_h1h  [(size_t)NN * C1];   // GAT1 pre-agg features (gathered)
__device__ float    g_out1 [(size_t)NN * C1];   // GAT1 output, GEMM2 input (fp32)
__device__ __half   g_h2h  [(size_t)NN * HID];  // GAT2 pre-agg features (gathered)
__device__ float    g_out2 [(size_t)NN * HID];
__device__ float    g_as1 [NN * HEADS];
__device__ float    g_ad1 [NN * HEADS];
__device__ float    g_den1[NN * HEADS];
__device__ float    g_e1  [(size_t)ETMX * HEADS];
__device__ float    g_as2 [NN];
__device__ float    g_ad2 [NN];
__device__ float    g_den2[NN];
__device__ float    g_e2  [ETMX];
__device__ float    g_pooled[HID];
// CSR by destination
__device__ int      g_deg   [NN];
__device__ int      g_rowptr[NN + 1];
__device__ int      g_cursor[NN];
__device__ int      g_csr_src[ETMX];
__device__ int      g_csr_eid[ETMX];

// ---------------- helpers ----------------------------------------------------
__device__ __forceinline__ void edge_sd(const int* ei, int E, int e, int& s, int& d) {
    if (e < E) { s = ei[e]; d = ei[E + e]; }
    else       { s = d = e - E; }           // self loop
}
__device__ __forceinline__ uint32_t f2tf32(float v) {
    uint32_t u;
    asm("cvt.rna.tf32.f32 %0, %1;" : "=r"(u) : "f"(v));
    return u;
}
__device__ __forceinline__ uint32_t smem_u32(const void* p) {
    uint32_t a;
    asm("{ .reg .u64 t; cvta.to.shared.u64 t, %1; cvt.u32.u64 %0, t; }"
        : "=r"(a) : "l"(p));
    return a;
}
// Async copies with zero-fill beyond `bytes`. Global src must be aligned to
// the cp size: 8B for A tiles (K=70 rows are only 8B-aligned), 16B for B.
__device__ __forceinline__ void cp8(uint32_t dst, const void* src, int bytes) {
    asm volatile("cp.async.ca.shared.global [%0], [%1], 8, %2;"
                 :: "r"(dst), "l"(src), "r"(bytes));
}
__device__ __forceinline__ void cp16(uint32_t dst, const void* src, int bytes) {
    asm volatile("cp.async.ca.shared.global [%0], [%1], 16, %2;"
                 :: "r"(dst), "l"(src), "r"(bytes));
}
#define CP_COMMIT()  asm volatile("cp.async.commit_group;" ::: "memory")
#define CP_WAIT(n)   asm volatile("cp.async.wait_group %0;" :: "n"(n) : "memory")

// ---------------- tf32 mma.sync GEMM, cp.async double-buffered ---------------
// C[M,N](half) = A[M,K](fp32) @ B[K,N](fp32). tf32 in (rna cvt at frag load),
// fp32 accum. CTA 64x128, 4 warps, warp = 64(M)x32(N) of m16n8k8 frags.
#define GBM 64
#define GBN 128
#define GBK 32
#define APAD 36     // 64x36 words per A stage (rows 144B: 16B-aligned)
#define BPAD 136    // 32x136 words per B stage (rows 544B: 16B-aligned)
#define ASTG (GBM * APAD)
#define BSTG (GBK * BPAD)
#define SMEM_GEMM ((2 * ASTG + 2 * BSTG) * 4)   // 53248 bytes

__global__ __launch_bounds__(128) void gemm_mma(
    const float* __restrict__ A, const float* __restrict__ B,
    __half* __restrict__ C, int M, int N, int K)
{
    extern __shared__ uint32_t dsm[];
    const uint32_t sb = smem_u32(dsm);
    const uint32_t sbB = sb + 2 * ASTG * 4;

    const int tid  = threadIdx.x;
    const int wid  = tid >> 5;
    const int lane = tid & 31;
    const int grp  = lane >> 2;       // 0..7
    const int sub  = lane & 3;        // 0..3
    const int bm = blockIdx.y * GBM;
    const int bn = blockIdx.x * GBN;
    const int wn = wid * 32;

    float acc[4][4][4];
#pragma unroll
    for (int i = 0; i < 4; i++)
#pragma unroll
        for (int j = 0; j < 4; j++)
#pragma unroll
            for (int r = 0; r < 4; r++) acc[i][j][r] = 0.f;

    const int T = (K + GBK - 1) / GBK;

    // Issue async copies for k-tile kt into stage st.
    auto issue = [&](int kt, int st) {
        const int k0 = kt * GBK;
        // A tile 64x32 fp32 as 8B chunks (1024 chunks, 8/thread).
        // addr = gm*K*4 + gk*4; K*4 = 280 for X (mult of 8), gk even -> 8B ok.
#pragma unroll
        for (int it = 0; it < 8; it++) {
            int id = it * 128 + tid;
            int r = id >> 4, c2 = (id & 15) << 1;   // word offset 0,2,..,30
            int gm = bm + r, gk = k0 + c2;
            int nb = 0;
            const float* src = A;
            if (gm < M && gk < K) {
                src = &A[(size_t)gm * K + gk];
                int rem = (K - gk) * 4;
                nb = rem < 8 ? rem : 8;
            }
            cp8(sb + ((st * GBM + r) * APAD + c2) * 4, src, nb);
        }
        // B tile 32x128 fp32 as 16B chunks (1024 chunks, 8/thread).
#pragma unroll
        for (int it = 0; it < 8; it++) {
            int id = it * 128 + tid;
            int kr = id >> 5, c4 = (id & 31) << 2;
            int gk = k0 + kr;
            const float* src = (gk < K) ? &B[(size_t)gk * N + bn + c4] : B;
            cp16(sbB + ((st * GBK + kr) * BPAD + c4) * 4, src, (gk < K) ? 16 : 0);
        }
        CP_COMMIT();
    };

    issue(0, 0);
    for (int kt = 0; kt < T; kt++) {
        const int st = kt & 1;
        if (kt + 1 < T) {
            issue(kt + 1, st ^ 1);
            CP_WAIT(1);               // tile kt resident; kt+1 in flight
        } else {
            CP_WAIT(0);
        }
        __syncthreads();

        const uint32_t* AsS = dsm + st * ASTG;
        const uint32_t* BsS = dsm + 2 * ASTG + st * BSTG;

#pragma unroll
        for (int kk = 0; kk < 4; kk++) {          // 4 kfrags of 8
            const int kf = kk * 8;
            uint32_t a[4][4], b[4][2];
#pragma unroll
            for (int i = 0; i < 4; i++) {
                int m0 = i * 16;
                a[i][0] = f2tf32(__uint_as_float(AsS[(m0 + grp    ) * APAD + kf + sub    ]));
                a[i][1] = f2tf32(__uint_as_float(AsS[(m0 + 8 + grp) * APAD + kf + sub    ]));
                a[i][2] = f2tf32(__uint_as_float(AsS[(m0 + grp    ) * APAD + kf + 4 + sub]));
                a[i][3] = f2tf32(__uint_as_float(AsS[(m0 + 8 + grp) * APAD + kf + 4 + sub]));
            }
#pragma unroll
            for (int j = 0; j < 4; j++) {
                int n0 = wn + j * 8;
                b[j][0] = f2tf32(__uint_as_float(BsS[(kf + sub    ) * BPAD + n0 + grp]));
                b[j][1] = f2tf32(__uint_as_float(BsS[(kf + 4 + sub) * BPAD + n0 + grp]));
            }
#pragma unroll
            for (int i = 0; i < 4; i++)
#pragma unroll
                for (int j = 0; j < 4; j++)
                    asm volatile(
                        "mma.sync.aligned.m16n8k8.row.col.f32.tf32.tf32.f32 "
                        "{%0,%1,%2,%3}, {%4,%5,%6,%7}, {%8,%9}, {%0,%1,%2,%3};"
                        : "+f"(acc[i][j][0]), "+f"(acc[i][j][1]),
                          "+f"(acc[i][j][2]), "+f"(acc[i][j][3])
                        : "r"(a[i][0]), "r"(a[i][1]), "r"(a[i][2]), "r"(a[i][3]),
                          "r"(b[j][0]), "r"(b[j][1]));
        }
        __syncthreads();
    }

    // Epilogue: half2 stores. c0/c1 at (row, col), c2/c3 at (row+8, col).
#pragma unroll
    for (int i = 0; i < 4; i++) {
#pragma unroll
        for (int j = 0; j < 4; j++) {
            int col = bn + wn + j * 8 + sub * 2;
            int r0 = bm + i * 16 + grp;
            if (r0 < M)
                *(__half2*)&C[(size_t)r0 * N + col] =
                    __floats2half2_rn(acc[i][j][0], acc[i][j][1]);
            if (r0 + 8 < M)
                *(__half2*)&C[(size_t)(r0 + 8) * N + col] =
                    __floats2half2_rn(acc[i][j][2], acc[i][j][3]);
        }
    }
}

// ---------------- CSR build --------------------------------------------------
__global__ void init_all() {
    int i = blockIdx.x * blockDim.x + threadIdx.x;
    if (i < NN * HEADS) g_den1[i] = 0.f;
    if (i < NN) { g_den2[i] = 0.f; g_deg[i] = 0; }
    if (i < HID) g_pooled[i] = 0.f;
}

__global__ void csr_count(const int* __restrict__ ei, int E, int n) {
    int e = blockIdx.x * blockDim.x + threadIdx.x;
    if (e >= E + n) return;
    int d = (e < E) ? ei[E + e] : (e - E);
    atomicAdd(&g_deg[d], 1);
}

// Single-block exclusive scan of g_deg -> g_rowptr/g_cursor. 1024 threads.
__global__ __launch_bounds__(1024) void scan_deg(int n, int etot) {
    __shared__ int s_ws[32];
    __shared__ int s_tot;
    const int t = threadIdx.x, lane = t & 31, wid = t >> 5;
    int carry = 0;
    for (int base = 0; base < n; base += 1024) {
        int i = base + t;
        int v = (i < n) ? g_deg[i] : 0;
        int x = v;
#pragma unroll
        for (int o = 1; o < 32; o <<= 1) {
            int y = __shfl_up_sync(0xffffffffu, x, o);
            if (lane >= o) x += y;
        }
        if (lane == 31) s_ws[wid] = x;
        __syncthreads();
        if (wid == 0) {
            int y = s_ws[lane];
#pragma unroll
            for (int o = 1; o < 32; o <<= 1) {
                int z = __shfl_up_sync(0xffffffffu, y, o);
                if (lane >= o) y += z;
            }
            s_ws[lane] = y;
            if (lane == 31) s_tot = y;
        }
        __syncthreads();
        int incl = x + (wid ? s_ws[wid - 1] : 0) + carry;
        if (i < n) { g_rowptr[i] = incl - v; g_cursor[i] = incl - v; }
        carry += s_tot;
        __syncthreads();
    }
    if (t == 0) g_rowptr[n] = etot;
}

__global__ void csr_scatter(const int* __restrict__ ei, int E, int n) {
    int e = blockIdx.x * blockDim.x + threadIdx.x;
    if (e >= E + n) return;
    int s, d; edge_sd(ei, E, e, s, d);
    int pos = atomicAdd(&g_cursor[d], 1);
    g_csr_src[pos] = s;
    g_csr_eid[pos] = e;
}

// ---------------- layer 1 ----------------------------------------------------
// per (node, head) dots with att vectors; h1 read as half2.
__global__ void att1_kernel(const float* __restrict__ asrc,
                            const float* __restrict__ adst, int n)
{
    int wid = (blockIdx.x * blockDim.x + threadIdx.x) >> 5;
    int lane = threadIdx.x & 31;
    if (wid >= n * HEADS) return;
    int node = wid >> 2, h = wid & 3;
    const __half2* x = (const __half2*)(g_h1h + (size_t)node * C1 + h * HID);
    const float* s = asrc + h * HID;
    const float* d = adst + h * HID;
    float ss = 0.f, dd = 0.f;
#pragma unroll
    for (int i = lane; i < HID / 2; i += 32) {
        float2 v = __half22float2(x[i]);
        ss = fmaf(v.x, s[2 * i], fmaf(v.y, s[2 * i + 1], ss));
        dd = fmaf(v.x, d[2 * i], fmaf(v.y, d[2 * i + 1], dd));
    }
#pragma unroll
    for (int o = 16; o; o >>= 1) {
        ss += __shfl_down_sync(0xffffffffu, ss, o);
        dd += __shfl_down_sync(0xffffffffu, dd, o);
    }
    if (lane == 0) { g_as1[node * HEADS + h] = ss; g_ad1[node * HEADS + h] = dd; }
}

// Fused leaky_relu + exp + denom (no segment-max: scores bounded, exp safe;
// alpha = exp(e)/sum exp(e) identical to the max-shifted form).
__global__ void edge_fused1(const int* __restrict__ ei, int E, int n) {
    int e = blockIdx.x * blockDim.x + threadIdx.x;
    if (e >= E + n) return;
    int s, d; edge_sd(ei, E, e, s, d);
    float4 a = *(const float4*)&g_as1[s * HEADS];
    float4 b = *(const float4*)&g_ad1[d * HEADS];
    float v[4] = {a.x + b.x, a.y + b.y, a.z + b.z, a.w + b.w};
    float ex[4];
#pragma unroll
    for (int h = 0; h < 4; h++) {
        float t = v[h] > 0.f ? v[h] : 0.2f * v[h];
        ex[h] = expf(t);
        atomicAdd(&g_den1[d * HEADS + h], ex[h]);
    }
    *(float4*)&g_e1[(size_t)e * HEADS] = make_float4(ex[0], ex[1], ex[2], ex[3]);
}

// One block per dst node; gathers HALF h1 rows, fp32 accum.
// Bias+ReLU fused; writes fp32 out1 (GEMM2 A path stays fp32/coalesced).
#define CHUNK 64
__global__ __launch_bounds__(256) void aggregate1_csr(const float* __restrict__ b1, int n) {
    int d = blockIdx.x;
    int t = threadIdx.x;
    int beg = g_rowptr[d], end = g_rowptr[d + 1];
    int h = t >> 6;                  // 0..3
    int c = (t & 63) << 2;           // 0..252

    __shared__ float s_invden[HEADS];
    __shared__ int   s_src[CHUNK];
    __shared__ float s_alpha[CHUNK * HEADS];
    if (t < HEADS) s_invden[t] = 1.f / (g_den1[d * HEADS + t] + 1e-16f);
    __syncthreads();

    float4 acc = make_float4(0.f, 0.f, 0.f, 0.f);
    for (int cb = beg; cb < end; cb += CHUNK) {
        int m = min(CHUNK, end - cb);
        if (t < m) {
            int pos = cb + t;
            int e = g_csr_eid[pos];
            s_src[t] = g_csr_src[pos];
            float4 ex = *(const float4*)&g_e1[(size_t)e * HEADS];
            s_alpha[t * 4 + 0] = ex.x * s_invden[0];
            s_alpha[t * 4 + 1] = ex.y * s_invden[1];
            s_alpha[t * 4 + 2] = ex.z * s_invden[2];
            s_alpha[t * 4 + 3] = ex.w * s_invden[3];
        }
        __syncthreads();
        for (int j = 0; j < m; j++) {
            int s = s_src[j];
            float a = s_alpha[j * 4 + h];
            uint2 u = *(const uint2*)&g_h1h[(size_t)s * C1 + h * HID + c];
            float2 f0 = __half22float2(*(__half2*)&u.x);
            float2 f1 = __half22float2(*(__half2*)&u.y);
            acc.x = fmaf(a, f0.x, acc.x);
            acc.y = fmaf(a, f0.y, acc.y);
            acc.z = fmaf(a, f1.x, acc.z);
            acc.w = fmaf(a, f1.y, acc.w);
        }
        __syncthreads();
    }
    float4 bv = *(const float4*)&b1[h * HID + c];
    float4 o = make_float4(fmaxf(acc.x + bv.x, 0.f), fmaxf(acc.y + bv.y, 0.f),
                           fmaxf(acc.z + bv.z, 0.f), fmaxf(acc.w + bv.w, 0.f));
    *(float4*)&g_out1[(size_t)d * C1 + h * HID + c] = o;
}

// ---------------- layer 2 ----------------------------------------------------
__global__ void att2_kernel(const float* __restrict__ asrc,
                            const float* __restrict__ adst, int n)
{
    int wid = (blockIdx.x * blockDim.x + threadIdx.x) >> 5;
    int lane = threadIdx.x & 31;
    if (wid >= n) return;
    const __half2* x = (const __half2*)(g_h2h + (size_t)wid * HID);
    float ss = 0.f, dd = 0.f;
#pragma unroll
    for (int i = lane; i < HID / 2; i += 32) {
        float2 v = __half22float2(x[i]);
        ss = fmaf(v.x, asrc[2 * i], fmaf(v.y, asrc[2 * i + 1], ss));
        dd = fmaf(v.x, adst[2 * i], fmaf(v.y, adst[2 * i + 1], dd));
    }
#pragma unroll
    for (int o = 16; o; o >>= 1) {
        ss += __shfl_down_sync(0xffffffffu, ss, o);
        dd += __shfl_down_sync(0xffffffffu, dd, o);
    }
    if (lane == 0) { g_as2[wid] = ss; g_ad2[wid] = dd; }
}

__global__ void edge_fused2(const int* __restrict__ ei, int E, int n) {
    int e = blockIdx.x * blockDim.x + threadIdx.x;
    if (e >= E + n) return;
    int s, d; edge_sd(ei, E, e, s, d);
    float v = g_as2[s] + g_ad2[d];
    v = v > 0.f ? v : 0.2f * v;
    float ex = expf(v);
    g_e2[e] = ex;
    atomicAdd(&g_den2[d], ex);
}

// 4 dst nodes per 256-thread block; 64 lanes per node. Bias fused.
__global__ __launch_bounds__(256) void aggregate2_csr(const float* __restrict__ b2, int n) {
    int sub = threadIdx.x >> 6;
    int lane = threadIdx.x & 63;
    int d = blockIdx.x * 4 + sub;
    if (d >= n) return;
    int beg = g_rowptr[d], end = g_rowptr[d + 1];
    float invden = 1.f / (g_den2[d] + 1e-16f);
    int c = lane << 2;
    float4 acc = make_float4(0.f, 0.f, 0.f, 0.f);
    for (int k = beg; k < end; k++) {
        int s = g_csr_src[k];
        int e = g_csr_eid[k];
        float a = g_e2[e] * invden;
        uint2 u = *(const uint2*)&g_h2h[(size_t)s * HID + c];
        float2 f0 = __half22float2(*(__half2*)&u.x);
        float2 f1 = __half22float2(*(__half2*)&u.y);
        acc.x = fmaf(a, f0.x, acc.x);
        acc.y = fmaf(a, f0.y, acc.y);
        acc.z = fmaf(a, f1.x, acc.z);
        acc.w = fmaf(a, f1.y, acc.w);
    }
    float4 bv = *(const float4*)&b2[c];
    *(float4*)&g_out2[(size_t)d * HID + c] =
        make_float4(acc.x + bv.x, acc.y + bv.y, acc.z + bv.z, acc.w + bv.w);
}

// relu + column-sum pooling
__global__ void pool_kernel(int n) {
    int c = threadIdx.x;        // 256
    float acc = 0.f;
    for (int r = blockIdx.x; r < n; r += gridDim.x)
        acc += fmaxf(g_out2[(size_t)r * HID + c], 0.f);
    atomicAdd(&g_pooled[c], acc);
}

// mean -> Linear(256,128) -> exact GELU -> Linear(128,1)
__global__ void final_kernel(const float* __restrict__ Wv1, const float* __restrict__ bv1,
                             const float* __restrict__ Wv2, const float* __restrict__ bv2,
                             float* __restrict__ out, int n)
{
    __shared__ float p[HID];
    __shared__ float red[128];
    int t = threadIdx.x;        // 128
    float inv = 1.f / (float)n;
    p[t]       = g_pooled[t] * inv;
    p[t + 128] = g_pooled[t + 128] * inv;
    __syncthreads();
    float acc = bv1[t];
#pragma unroll 8
    for (int k = 0; k < HID; k++) acc = fmaf(p[k], Wv1[k * 128 + t], acc);
    float g = 0.5f * acc * (1.f + erff(acc * 0.70710678118654752f));
    red[t] = g * Wv2[t];
    __syncthreads();
#pragma unroll
    for (int o = 64; o; o >>= 1) {
        if (t < o) red[t] += red[t + o];
        __syncthreads();
    }
    if (t == 0) out[0] = red[0] + bv2[0];
}

// ---------------- launcher ---------------------------------------------------
extern "C" void kernel_launch(void* const* d_in, const int* in_sizes, int n_in,
                              void* d_out, int out_size)
{
    const float* X   = (const float*)d_in[0];
    const int*   EI  = (const int*)  d_in[1];
    // d_in[2] edge_attr: ignored (GATConv has no edge_dim)
    const float* W1  = (const float*)d_in[3];
    const float* as1 = (const float*)d_in[4];
    const float* ad1 = (const float*)d_in[5];
    const float* b1  = (const float*)d_in[6];
    const float* W2  = (const float*)d_in[7];
    const float* as2 = (const float*)d_in[8];
    const float* ad2 = (const float*)d_in[9];
    const float* b2  = (const float*)d_in[10];
    const float* Wv1 = (const float*)d_in[11];
    const float* bv1 = (const float*)d_in[12];
    const float* Wv2 = (const float*)d_in[13];
    const float* bv2 = (const float*)d_in[14];
    float* out = (float*)d_out;

    int n = in_sizes[0] / FIN;       // 10000
    int E = in_sizes[1] / 2;         // 160000
    int etot = E + n;
    int mtiles = (n + GBM - 1) / GBM;    // 157

    __half *p_h1h, *p_h2h;
    float  *p_out1;
    cudaGetSymbolAddress((void**)&p_h1h,  g_h1h);
    cudaGetSymbolAddress((void**)&p_out1, g_out1);
    cudaGetSymbolAddress((void**)&p_h2h,  g_h2h);

    cudaFuncSetAttribute(gemm_mma, cudaFuncAttributeMaxDynamicSharedMemorySize, SMEM_GEMM);

    // ---- init + CSR build ----
    init_all<<<(n * HEADS + 255) / 256, 256>>>();
    csr_count<<<(etot + 255) / 256, 256>>>(EI, E, n);
    scan_deg<<<1, 1024>>>(n, etot);
    csr_scatter<<<(etot + 255) / 256, 256>>>(EI, E, n);

    // ---- layer 1: h1 = X @ W1 (tf32 mma.sync + cp.async, half out) ----
    {
        dim3 grid(C1 / GBN, mtiles);
        gemm_mma<<<grid, 128, SMEM_GEMM>>>(X, W1, p_h1h, n, C1, FIN);
    }
    att1_kernel<<<(n * HEADS * 32 + 255) / 256, 256>>>(as1, ad1, n);
    edge_fused1<<<(etot + 255) / 256, 256>>>(EI, E, n);
    aggregate1_csr<<<n, 256>>>(b1, n);

    // ---- layer 2: h2 = out1(fp32) @ W2 (half out) ----
    {
        dim3 grid(HID / GBN, mtiles);
        gemm_mma<<<grid, 128, SMEM_GEMM>>>(p_out1, W2, p_h2h, n, HID, C1);
    }
    att2_kernel<<<(n * 32 + 255) / 256, 256>>>(as2, ad2, n);
    edge_fused2<<<(etot + 255) / 256, 256>>>(EI, E, n);
    aggregate2_csr<<<(n + 3) / 4, 256>>>(b2, n);

    // ---- head ----
    pool_kernel<<<128, 256>>>(n);
    final_kernel<<<1, 128>>>(Wv1, bv1, Wv2, bv2, out, n);
}